// round 12
// baseline (speedup 1.0000x reference)
#include <cuda_runtime.h>
#include <cstdint>

// ============================================================================
// ShiftConv as gather-GEMM, fp16 mma.sync m16n8k16 (fp32 accum):
//   out[n,d,y,x] = sum_c x[n,c,y+sh[c],x+sw[c]] * W[c,d] + bias[d]
// M = 131072 pixels, K = 256, N = 256.
// PERSISTENT: 148 CTAs x 1024 threads (32 warps), each loops ~7 M-tiles of 128.
// B (256x256 fp16 = 128 KB) resident in smem. A: 3-buffer ring, gather 2 ahead.
// Warp tile 32x32 (4 M-warps x 8 N-warps) -> 64 regs/thread, 8 warps/SMSP
// so LDS->MMA dependency stalls are covered by other warps.
// ============================================================================

#define CIN   256
#define NOUT  256
#define HW    4096
#define NTILE 1024           // 131072 / 128
#define GRID  148

#define B_BYTES  131072      // f4[8 s][256 n][4 a']
#define A_BYTES  8192        // f4[2 ks][8 g][8 r][4 a'] per ring slot
#define SMEM_BYTES (B_BYTES + 3 * A_BYTES + 2 * 256 * 4)   // 157696

__device__ float4 g_wp[8192];   // packed fp16 weight, 128 KB

static __device__ __forceinline__ uint32_t f16x2(float hi, float lo) {
    uint32_t d;
    asm("cvt.rn.f16x2.f32 %0, %1, %2;" : "=r"(d) : "f"(hi), "f"(lo));
    return d;
}

// --- prep: pack W into fp16 f4 slots, fragment-paired + pre-swizzled ---
// f4 index: s(8)|n(256)|a'(4); a = a' ^ ((n>>1)&3); c0 = s*32 + a*2
// words: w0={W[c0],W[c0+1]}, w1={+8,+9}, w2={+16,+17}, w3={+24,+25} (all @ n)
__global__ void pack_w_kernel(const float* __restrict__ w) {
    int t = blockIdx.x * 256 + threadIdx.x;     // 0..8191
    int ap = t & 3;
    int n  = (t >> 2) & 255;
    int s  = t >> 10;
    int a  = ap ^ ((n >> 1) & 3);
    int c0 = s * 32 + a * 2;
    float4 v;
    v.x = __uint_as_float(f16x2(w[(c0 +  1) * NOUT + n], w[(c0     ) * NOUT + n]));
    v.y = __uint_as_float(f16x2(w[(c0 +  9) * NOUT + n], w[(c0 +  8) * NOUT + n]));
    v.z = __uint_as_float(f16x2(w[(c0 + 17) * NOUT + n], w[(c0 + 16) * NOUT + n]));
    v.w = __uint_as_float(f16x2(w[(c0 + 25) * NOUT + n], w[(c0 + 24) * NOUT + n]));
    g_wp[t] = v;
}

static __device__ __forceinline__ void mma_f16(float* c, uint32_t a0, uint32_t a1,
                                               uint32_t a2, uint32_t a3,
                                               uint32_t b0, uint32_t b1) {
    asm volatile(
        "mma.sync.aligned.m16n8k16.row.col.f32.f16.f16.f32 "
        "{%0,%1,%2,%3}, {%4,%5,%6,%7}, {%8,%9}, {%0,%1,%2,%3};"
        : "+f"(c[0]), "+f"(c[1]), "+f"(c[2]), "+f"(c[3])
        : "r"(a0), "r"(a1), "r"(a2), "r"(a3), "r"(b0), "r"(b1));
}

static __device__ __forceinline__ void cp_async16cg(uint32_t dst, const void* src) {
    asm volatile("cp.async.cg.shared.global [%0], [%1], 16;"
                 :: "r"(dst), "l"(src) : "memory");
}

static __device__ __forceinline__ void lds128(uint32_t& r0, uint32_t& r1,
                                              uint32_t& r2, uint32_t& r3, uint32_t a) {
    asm volatile("ld.shared.v4.b32 {%0,%1,%2,%3}, [%4];"
                 : "=r"(r0), "=r"(r1), "=r"(r2), "=r"(r3) : "r"(a));
}

static __device__ __forceinline__ void lds64(uint32_t& r0, uint32_t& r1, uint32_t a) {
    asm volatile("ld.shared.v2.b32 {%0,%1}, [%2];" : "=r"(r0), "=r"(r1) : "r"(a));
}

static __device__ __forceinline__ void sts32(uint32_t addr, uint32_t v) {
    asm volatile("st.shared.b32 [%0], %1;" :: "r"(addr), "r"(v) : "memory");
}

// ============================================================================
__global__ __launch_bounds__(1024, 1) void shiftconv_mma(
    const float* __restrict__ x,
    const float* __restrict__ bias,
    const int* __restrict__ shift_h,
    const int* __restrict__ shift_w,
    float* __restrict__ out)
{
    extern __shared__ float smem[];
    // [B 128KB | A ring 3x8KB | shw 256 | bias 256]
    int*   shw_s  = (int*)(smem + (B_BYTES + 3 * A_BYTES) / 4);
    float* bias_s = (float*)(shw_s + 256);

    int tid  = threadIdx.x;
    int lane = tid & 31;
    int wid  = tid >> 5;
    int warp_m = wid & 3;        // 4 M-warps (32 rows each)
    int warp_n = wid >> 2;       // 8 N-warps (32 cols each)

    if (tid < 256) {
        shw_s[tid]  = (shift_h[tid] << 16) | (shift_w[tid] & 0xffff);
        bias_s[tid] = bias[tid];
    }

    uint32_t b_smem = (uint32_t)__cvta_generic_to_shared(smem);
    uint32_t a_smem = b_smem + B_BYTES;

    // ---- load ALL of B once (128 KB, 8 cp.async per thread) ----
    #pragma unroll
    for (int it = 0; it < 8; ++it) {
        int g = it * 1024 + tid;
        cp_async16cg(b_smem + (uint32_t)g * 16, g_wp + g);
    }
    asm volatile("cp.async.commit_group;" ::: "memory");

    // gather ownership: pixel mloc (0..127), channel quad kg (0..7, 4 ch each)
    int mloc = tid & 127;
    int kg   = tid >> 7;
    int xc   = mloc & 63;

    // A layout bytes: ks*4096 + g*512 + r*64 + a*16 + w*4
    // thread's channels c0 + kg*4 + {0..3}:
    //   ks = kg>>2, word w = ((kg>>1)&1)*2 + mhalf, slots a = (kg&1)*2 + {0,1}
    int sks   = kg >> 2;
    int sq    = kg & 1;
    int sw_w  = ((kg >> 1) & 1) * 2 + ((mloc >> 3) & 1);
    int sg    = mloc >> 4;
    int sr    = mloc & 7;
    int sswz  = (sr >> 1) & 3;
    uint32_t sts_base = (uint32_t)(sks * 4096 + sg * 512 + sr * 64 + sw_w * 4);

    // fragment bases (thread-constant swizzles)
    int fa = lane & 3;
    int fr = lane >> 2;
    uint32_t fswz = (uint32_t)((fa ^ ((fr >> 1) & 3)) * 16);
    // A: + ks*4096 + (warp_m*2 + mt)*512
    uint32_t a_tbase = (uint32_t)(warp_m * 2 * 512 + fr * 64) + fswz;
    // B: + s*16384 + nt*512 + ks*8
    uint32_t b_tbase = (uint32_t)((warp_n * 32 + fr) * 64) + fswz;

    #define GATHER(c0, p) do {                                                 \
        _Pragma("unroll")                                                      \
        for (int i = 0; i < 4; ++i) {                                          \
            int c  = (c0) + kg * 4 + i;                                        \
            int w_ = shw_s[c];                                                 \
            int sy = y + (w_ >> 16);                                           \
            int sx = xc + ((w_ << 16) >> 16);                                  \
            float v = 0.f;                                                     \
            if ((unsigned)sy < 64u && (unsigned)sx < 64u)                      \
                v = __ldg(xb + (size_t)c * HW + sy * 64 + sx);                 \
            p[i] = v;                                                          \
        }                                                                      \
    } while (0)

    #define STS_A(p, buf) do {                                                 \
        uint32_t base = a_smem + (uint32_t)((buf) * A_BYTES) + sts_base;       \
        _Pragma("unroll")                                                      \
        for (int j = 0; j < 2; ++j)                                            \
            sts32(base + (uint32_t)(((sq * 2 + j) ^ sswz) * 16),               \
                  f16x2(p[2 * j + 1], p[2 * j]));                              \
    } while (0)

    asm volatile("cp.async.wait_group 0;" ::: "memory");
    __syncthreads();   // B resident + tables ready

    // ======================= persistent tile loop =======================
    for (int t = blockIdx.x; t < NTILE; t += GRID) {
        int m0   = t << 7;
        int nimg = m0 >> 12;
        int pix0 = m0 & 4095;
        int y    = (pix0 + mloc) >> 6;
        const float* xb = x + (size_t)nimg * (CIN * HW);

        float acc[2][4][4];
        #pragma unroll
        for (int mt = 0; mt < 2; ++mt)
            #pragma unroll
            for (int nt = 0; nt < 4; ++nt)
                #pragma unroll
                for (int e = 0; e < 4; ++e) acc[mt][nt][e] = 0.f;

        // prologue: gather chunks 0 and 1, store chunk 0
        float p[2][4];
        GATHER(0,  p[0]);
        GATHER(32, p[1]);
        STS_A(p[0], 0);
        __syncthreads();

        // mainloop: 8 chunks of K=32, A ring of 3, gather 2 ahead
        #pragma unroll
        for (int s = 0; s < 8; ++s) {
            if (s < 7) STS_A(p[(s + 1) & 1], (s + 1) % 3);
            if (s < 6) GATHER((s + 2) * 32, p[s & 1]);

            uint32_t a_base = a_smem + (uint32_t)((s % 3) * A_BYTES);
            uint32_t b_base = b_smem + (uint32_t)(s * 16384) + b_tbase;

            #pragma unroll
            for (int ks = 0; ks < 2; ++ks) {
                uint32_t bf[4][2];
                #pragma unroll
                for (int nt = 0; nt < 4; ++nt)
                    lds64(bf[nt][0], bf[nt][1],
                          b_base + (uint32_t)(nt * 512 + ks * 8));
                uint32_t af[2][4];
                #pragma unroll
                for (int mt = 0; mt < 2; ++mt)
                    lds128(af[mt][0], af[mt][1], af[mt][2], af[mt][3],
                           a_base + a_tbase + (uint32_t)(ks * 4096 + mt * 512));
                #pragma unroll
                for (int mt = 0; mt < 2; ++mt)
                    #pragma unroll
                    for (int nt = 0; nt < 4; ++nt)
                        mma_f16(acc[mt][nt],
                                af[mt][0], af[mt][1], af[mt][2], af[mt][3],
                                bf[nt][0], bf[nt][1]);
            }
            __syncthreads();
        }

        // epilogue: bias + store out[n][d][pixel]
        float* ob = out + (size_t)nimg * (NOUT * HW) + pix0;
        #pragma unroll
        for (int mt = 0; mt < 2; ++mt) {
            int m_ = warp_m * 32 + mt * 16 + fr;
            #pragma unroll
            for (int nt = 0; nt < 4; ++nt) {
                int d_ = warp_n * 32 + nt * 8 + 2 * fa;
                float b0 = bias_s[d_], b1 = bias_s[d_ + 1];
                size_t o = (size_t)d_ * HW + m_;
                ob[o]          = acc[mt][nt][0] + b0;
                ob[o + HW]     = acc[mt][nt][1] + b1;
                ob[o + 8]      = acc[mt][nt][2] + b0;
                ob[o + HW + 8] = acc[mt][nt][3] + b1;
            }
        }
    }

    #undef GATHER
    #undef STS_A
}

// ============================================================================
extern "C" void kernel_launch(void* const* d_in, const int* in_sizes, int n_in,
                              void* d_out, int out_size) {
    const float* x      = (const float*)d_in[0];
    const float* weight = (const float*)d_in[1];
    const float* bias   = (const float*)d_in[2];
    const int*   sh     = (const int*)d_in[3];
    const int*   sw     = (const int*)d_in[4];
    float*       out    = (float*)d_out;

    static int attr_set = 0;
    if (!attr_set) {
        cudaFuncSetAttribute(shiftconv_mma,
                             cudaFuncAttributeMaxDynamicSharedMemorySize, SMEM_BYTES);
        attr_set = 1;
    }

    pack_w_kernel<<<32, 256>>>(weight);
    shiftconv_mma<<<GRID, 1024, SMEM_BYTES>>>(x, bias, sh, sw, out);
}

// round 13
// speedup vs baseline: 1.7074x; 1.7074x over previous
#include <cuda_runtime.h>
#include <cstdint>

// ============================================================================
// ShiftConv as gather-GEMM, fp16 mma.sync m16n8k16 (fp32 accum):
//   out[n,d,y,x] = sum_c x[n,c,y+sh[c],x+sw[c]] * W[c,d] + bias[d]
// M = 131072 pixels, K = 256, N = 256.
// PERSISTENT: 148 CTAs x 512 thr (16 warps, warp tile 64x32).
// B (256x256 fp16 = 128 KB) resident in smem.
// A staged as HALF-TILES (4 K-chunks = 32 KB), double-buffered:
//   2 barriers per tile (vs 8), 2-chunk MMA spans with zero syncs so the
//   compiler pipelines fragment LDS under MMA; gather LDGs issued a half
//   ahead and converted/stored between MMA blocks.
// ============================================================================

#define CIN   256
#define NOUT  256
#define HW    4096
#define NTILE 1024           // 131072 / 128
#define GRID  148

#define B_BYTES  131072      // f4[8 s][256 n][4 a']
#define A_HALF   32768       // 4 chunks x 8 KB (f4[2 ks][8 g][8 r][4 a'] each)
#define SMEM_BYTES (B_BYTES + 2 * A_HALF + 2 * 256 * 4)   // 198656

__device__ float4 g_wp[8192];   // packed fp16 weight, 128 KB

static __device__ __forceinline__ uint32_t f16x2(float hi, float lo) {
    uint32_t d;
    asm("cvt.rn.f16x2.f32 %0, %1, %2;" : "=r"(d) : "f"(hi), "f"(lo));
    return d;
}

// --- prep: pack W into fp16 f4 slots, fragment-paired + pre-swizzled ---
// f4 index: s(8)|n(256)|a'(4); a = a' ^ ((n>>1)&3); c0 = s*32 + a*2
// words: w0={W[c0],W[c0+1]}, w1={+8,+9}, w2={+16,+17}, w3={+24,+25} (all @ n)
__global__ void pack_w_kernel(const float* __restrict__ w) {
    int t = blockIdx.x * 256 + threadIdx.x;     // 0..8191
    int ap = t & 3;
    int n  = (t >> 2) & 255;
    int s  = t >> 10;
    int a  = ap ^ ((n >> 1) & 3);
    int c0 = s * 32 + a * 2;
    float4 v;
    v.x = __uint_as_float(f16x2(w[(c0 +  1) * NOUT + n], w[(c0     ) * NOUT + n]));
    v.y = __uint_as_float(f16x2(w[(c0 +  9) * NOUT + n], w[(c0 +  8) * NOUT + n]));
    v.z = __uint_as_float(f16x2(w[(c0 + 17) * NOUT + n], w[(c0 + 16) * NOUT + n]));
    v.w = __uint_as_float(f16x2(w[(c0 + 25) * NOUT + n], w[(c0 + 24) * NOUT + n]));
    g_wp[t] = v;
}

static __device__ __forceinline__ void mma_f16(float* c, uint32_t a0, uint32_t a1,
                                               uint32_t a2, uint32_t a3,
                                               uint32_t b0, uint32_t b1) {
    asm volatile(
        "mma.sync.aligned.m16n8k16.row.col.f32.f16.f16.f32 "
        "{%0,%1,%2,%3}, {%4,%5,%6,%7}, {%8,%9}, {%0,%1,%2,%3};"
        : "+f"(c[0]), "+f"(c[1]), "+f"(c[2]), "+f"(c[3])
        : "r"(a0), "r"(a1), "r"(a2), "r"(a3), "r"(b0), "r"(b1));
}

static __device__ __forceinline__ void cp_async16cg(uint32_t dst, const void* src) {
    asm volatile("cp.async.cg.shared.global [%0], [%1], 16;"
                 :: "r"(dst), "l"(src) : "memory");
}

static __device__ __forceinline__ void lds128(uint32_t& r0, uint32_t& r1,
                                              uint32_t& r2, uint32_t& r3, uint32_t a) {
    asm volatile("ld.shared.v4.b32 {%0,%1,%2,%3}, [%4];"
                 : "=r"(r0), "=r"(r1), "=r"(r2), "=r"(r3) : "r"(a));
}

static __device__ __forceinline__ void sts32(uint32_t addr, uint32_t v) {
    asm volatile("st.shared.b32 [%0], %1;" :: "r"(addr), "r"(v) : "memory");
}

// ============================================================================
__global__ __launch_bounds__(512, 1) void shiftconv_mma(
    const float* __restrict__ x,
    const float* __restrict__ bias,
    const int* __restrict__ shift_h,
    const int* __restrict__ shift_w,
    float* __restrict__ out)
{
    extern __shared__ float smem[];
    // [B 128KB | A half-buffers 2x32KB | shw 256 | bias 256]
    int*   shw_s  = (int*)(smem + (B_BYTES + 2 * A_HALF) / 4);
    float* bias_s = (float*)(shw_s + 256);

    int tid  = threadIdx.x;
    int lane = tid & 31;
    int wid  = tid >> 5;
    int warp_m = wid & 1;        // 2 M-warps (64 rows each)
    int warp_n = wid >> 1;       // 8 N-warps (32 cols each)

    if (tid < 256) {
        shw_s[tid]  = (shift_h[tid] << 16) | (shift_w[tid] & 0xffff);
        bias_s[tid] = bias[tid];
    }

    uint32_t b_smem = (uint32_t)__cvta_generic_to_shared(smem);
    uint32_t a_smem = b_smem + B_BYTES;

    // ---- issue load of ALL of B (128 KB, 16 cp.async per thread) ----
    #pragma unroll
    for (int it = 0; it < 16; ++it) {
        int g = it * 512 + tid;
        cp_async16cg(b_smem + (uint32_t)g * 16, g_wp + g);
    }
    asm volatile("cp.async.commit_group;" ::: "memory");

    // gather ownership: pixel mloc (0..127), channel octet kg (0..3)
    int mloc = tid & 127;
    int kg   = tid >> 7;
    int xc   = mloc & 63;

    // A per-chunk layout bytes: ks*4096 + g*512 + r*64 + a*16 + w*4
    int sks   = kg >> 1;
    int sw_w  = (kg & 1) * 2 + ((mloc >> 3) & 1);
    int sg    = mloc >> 4;
    int sr    = mloc & 7;
    int sswz  = (sr >> 1) & 3;
    uint32_t sts_base = (uint32_t)(sks * 4096 + sg * 512 + sr * 64 + sw_w * 4);

    // fragment bases (thread-constant swizzles)
    int fa = lane & 3;
    int fr = lane >> 2;
    uint32_t fswz = (uint32_t)((fa ^ ((fr >> 1) & 3)) * 16);
    uint32_t a_tbase = (uint32_t)(warp_m * 4 * 512 + fr * 64) + fswz;
    uint32_t b_tbase = (uint32_t)((warp_n * 32 + fr) * 64) + fswz;

    // gather 8 channels of one chunk for this thread (chunk base c0)
    #define GATHER(xb_, y_, c0, p) do {                                        \
        _Pragma("unroll")                                                      \
        for (int i = 0; i < 8; ++i) {                                          \
            int c  = (c0) + kg * 8 + i;                                        \
            int w_ = shw_s[c];                                                 \
            int sy = (y_) + (w_ >> 16);                                        \
            int sx = xc + ((w_ << 16) >> 16);                                  \
            float v = 0.f;                                                     \
            if ((unsigned)sy < 64u && (unsigned)sx < 64u)                      \
                v = __ldg((xb_) + (size_t)c * HW + sy * 64 + sx);              \
            p[i] = v;                                                          \
        }                                                                      \
    } while (0)

    // store one chunk's octet into half-buffer `buf`, chunk-in-half j
    #define STS_CH(p, buf, j) do {                                             \
        uint32_t base = a_smem + (uint32_t)((buf) * A_HALF + (j) * 8192)       \
                        + sts_base;                                            \
        _Pragma("unroll")                                                      \
        for (int a = 0; a < 4; ++a)                                            \
            sts32(base + (uint32_t)((a ^ sswz) * 16),                          \
                  f16x2(p[2 * a + 1], p[2 * a]));                              \
    } while (0)

    // MMA one chunk: half-buffer buf, chunk-in-half j, global chunk s_
    #define MMA_CH(buf, j, s_) do {                                            \
        uint32_t a_base = a_smem + (uint32_t)((buf) * A_HALF + (j) * 8192);    \
        uint32_t bb = b_smem + (uint32_t)((s_) * 16384) + b_tbase;             \
        uint32_t bf[4][4];                                                     \
        _Pragma("unroll")                                                      \
        for (int nt = 0; nt < 4; ++nt)                                         \
            lds128(bf[nt][0], bf[nt][1], bf[nt][2], bf[nt][3],                 \
                   bb + (uint32_t)(nt * 512));                                 \
        _Pragma("unroll")                                                      \
        for (int ks = 0; ks < 2; ++ks) {                                       \
            uint32_t af[4][4];                                                 \
            _Pragma("unroll")                                                  \
            for (int mt = 0; mt < 4; ++mt)                                     \
                lds128(af[mt][0], af[mt][1], af[mt][2], af[mt][3],             \
                       a_base + a_tbase + (uint32_t)(ks * 4096 + mt * 512));   \
            _Pragma("unroll")                                                  \
            for (int mt = 0; mt < 4; ++mt)                                     \
                _Pragma("unroll")                                              \
                for (int nt = 0; nt < 4; ++nt)                                 \
                    mma_f16(acc[mt][nt],                                       \
                            af[mt][0], af[mt][1], af[mt][2], af[mt][3],        \
                            bf[nt][2 * ks], bf[nt][2 * ks + 1]);               \
        }                                                                      \
    } while (0)

    __syncthreads();   // tables visible (B cp.async still in flight)

    // ---- prologue: gather + stage half (tile blockIdx.x, h=0) into buf 0 ----
    {
        int t0   = blockIdx.x;
        int m0   = t0 << 7;
        int pix0 = m0 & 4095;
        int y0   = (pix0 + mloc) >> 6;
        const float* xb0 = x + (size_t)(m0 >> 12) * (CIN * HW);
        float p[8];
        #pragma unroll
        for (int j = 0; j < 4; ++j) {
            GATHER(xb0, y0, j * 32, p);
            STS_CH(p, 0, j);
        }
    }
    asm volatile("cp.async.wait_group 0;" ::: "memory");
    __syncthreads();   // B resident + half 0 staged

    int pb = 0;   // buffer currently holding the half to consume

    // ======================= persistent tile loop =======================
    for (int t = blockIdx.x; t < NTILE; t += GRID) {
        int m0   = t << 7;
        int nimg = m0 >> 12;
        int pix0 = m0 & 4095;

        float acc[4][4][4];
        #pragma unroll
        for (int mt = 0; mt < 4; ++mt)
            #pragma unroll
            for (int nt = 0; nt < 4; ++nt)
                #pragma unroll
                for (int e = 0; e < 4; ++e) acc[mt][nt][e] = 0.f;

        #pragma unroll
        for (int h = 0; h < 2; ++h) {
            // ---- next half to prefetch: (t, 1) if h==0 else (t+GRID, 0) ----
            int nt_   = (h == 0) ? t : t + GRID;
            int nc0   = (h == 0) ? 128 : 0;
            bool dog  = nt_ < NTILE;
            int nm0   = nt_ << 7;
            int npix  = nm0 & 4095;
            int ny    = (npix + mloc) >> 6;
            const float* nxb = x + (size_t)(nm0 >> 12) * (CIN * HW);

            float p0[8], p1[8];
            if (dog) {                       // LDGs in flight during MMA below
                GATHER(nxb, ny, nc0,      p0);
                GATHER(nxb, ny, nc0 + 32, p1);
            }

            MMA_CH(pb, 0, h * 4 + 0);
            MMA_CH(pb, 1, h * 4 + 1);

            if (dog) {
                STS_CH(p0, pb ^ 1, 0);
                STS_CH(p1, pb ^ 1, 1);
                GATHER(nxb, ny, nc0 + 64, p0);
                GATHER(nxb, ny, nc0 + 96, p1);
            }

            MMA_CH(pb, 2, h * 4 + 2);
            MMA_CH(pb, 3, h * 4 + 3);

            if (dog) {
                STS_CH(p0, pb ^ 1, 2);
                STS_CH(p1, pb ^ 1, 3);
            }

            if (h == 1) {
                // ---- epilogue: bias + store out[n][d][pixel] ----
                float* ob = out + (size_t)nimg * (NOUT * HW) + pix0;
                #pragma unroll
                for (int mt = 0; mt < 4; ++mt) {
                    int m_ = warp_m * 64 + mt * 16 + fr;
                    #pragma unroll
                    for (int nt2 = 0; nt2 < 4; ++nt2) {
                        int d_ = warp_n * 32 + nt2 * 8 + 2 * fa;
                        float b0 = bias_s[d_], b1 = bias_s[d_ + 1];
                        size_t o = (size_t)d_ * HW + m_;
                        ob[o]          = acc[mt][nt2][0] + b0;
                        ob[o + HW]     = acc[mt][nt2][1] + b1;
                        ob[o + 8]      = acc[mt][nt2][2] + b0;
                        ob[o + HW + 8] = acc[mt][nt2][3] + b1;
                    }
                }
            }

            __syncthreads();   // half pb fully consumed; pb^1 fully staged
            pb ^= 1;
        }
    }

    #undef GATHER
    #undef STS_CH
    #undef MMA_CH
}

// ============================================================================
extern "C" void kernel_launch(void* const* d_in, const int* in_sizes, int n_in,
                              void* d_out, int out_size) {
    const float* x      = (const float*)d_in[0];
    const float* weight = (const float*)d_in[1];
    const float* bias   = (const float*)d_in[2];
    const int*   sh     = (const int*)d_in[3];
    const int*   sw     = (const int*)d_in[4];
    float*       out    = (float*)d_out;

    static int attr_set = 0;
    if (!attr_set) {
        cudaFuncSetAttribute(shiftconv_mma,
                             cudaFuncAttributeMaxDynamicSharedMemorySize, SMEM_BYTES);
        attr_set = 1;
    }

    pack_w_kernel<<<32, 256>>>(weight);
    shiftconv_mma<<<GRID, 512, SMEM_BYTES>>>(x, bias, sh, sw, out);
}